// round 15
// baseline (speedup 1.0000x reference)
#include <cuda_runtime.h>
#include <cuda_bf16.h>
#include <math.h>
#include <stdint.h>
#include <string.h>

// ---------------------------------------------------------------------------
// SimpleHGN forward, round 15:
//  - fused_gat8: 2-deep software pipeline on the srcS->el index chain
//    (both softmax and aggregation passes)
//  - proj GEMM -> 256-thread / 2-CTA-per-SM variant (round-14 pattern)
//  - everything else identical to the 574.4us round-14 kernel
// ---------------------------------------------------------------------------

#define N_NODES 50000
#define N_EDGES 800000
#define N0 20000
#define N1 17000
#define N2 13000
#define SCAN_B 512
#define SCAN_NB ((N_NODES + SCAN_B - 1) / SCAN_B)

#define OFF_FCW0 0
#define OFF_FCW1 8192
#define OFF_FCW2 24576
#define OFF_W0   28672
#define OFF_W1C  45056
#define OFF_BCAT 176128
#define W_TOTAL  184320

// ------------------------------ side stream (created at library load) ------
struct StreamHolder {
    cudaStream_t s;
    cudaEvent_t a, b;
    StreamHolder() {
        cudaStreamCreateWithFlags(&s, cudaStreamNonBlocking);
        cudaEventCreateWithFlags(&a, cudaEventDisableTiming);
        cudaEventCreateWithFlags(&b, cudaEventDisableTiming);
    }
};
static StreamHolder g_sh;

// ------------------------------ scratch ------------------------------------
__device__ int   g_cnt[N_NODES];
__device__ int   g_rowptr[N_NODES + 1];
__device__ int   g_cursor[N_NODES];
__device__ int   g_bsum[SCAN_NB];
__device__ int   g_boff[SCAN_NB];
__device__ int   g_srcS[N_EDGES];
__device__ int   g_etS[N_EDGES];

__device__ float g_fr[(size_t)N_NODES * 512];
__device__ float g_f2[N_NODES * 32];
__device__ float g_a0[N_EDGES * 8];
__device__ float g_el[N_NODES * 8];
__device__ float g_er[N_NODES * 8];
__device__ float g_etatt[3 * 6 * 8];
__device__ uint16_t g_wh[W_TOTAL];
__device__ uint16_t g_wl[W_TOTAL];

__device__ uint16_t g_x0h[N0 * 128], g_x0l[N0 * 128];
__device__ uint16_t g_x1h[N1 * 256], g_x1l[N1 * 256];
__device__ uint16_t g_x2h[N2 * 64],  g_x2l[N2 * 64];
__device__ uint16_t g_h0h[N_NODES * 64],  g_h0l[N_NODES * 64];
__device__ uint16_t g_hAh[N_NODES * 256], g_hAl[N_NODES * 256];
__device__ uint16_t g_hBh[N_NODES * 256], g_hBl[N_NODES * 256];

// ------------------------------ helpers ------------------------------------
__device__ __forceinline__ uint32_t smem_u32(const void* p) {
    uint32_t a;
    asm("{ .reg .u64 t; cvta.to.shared.u64 t, %1; cvt.u32.u64 %0, t; }"
        : "=r"(a) : "l"(p));
    return a;
}

__device__ __forceinline__ void cp16(uint32_t dst, const void* src, int sz) {
    asm volatile("cp.async.cg.shared.global [%0], [%1], 16, %2;"
                 :: "r"(dst), "l"(src), "r"(sz) : "memory");
}
#define CP_COMMIT() asm volatile("cp.async.commit_group;" ::: "memory")
#define CP_WAIT1()  asm volatile("cp.async.wait_group 1;" ::: "memory")

#define LDSM_X4(r, addr) \
    asm volatile("ldmatrix.sync.aligned.m8n8.x4.shared.b16 {%0,%1,%2,%3}, [%4];" \
                 : "=r"((r)[0]), "=r"((r)[1]), "=r"((r)[2]), "=r"((r)[3]) \
                 : "r"(addr))

__device__ __forceinline__ void mma_bf16(float* c, uint32_t a0, uint32_t a1,
                                         uint32_t a2, uint32_t a3,
                                         uint32_t b0, uint32_t b1) {
    asm volatile(
        "mma.sync.aligned.m16n8k16.row.col.f32.bf16.bf16.f32 "
        "{%0,%1,%2,%3}, {%4,%5,%6,%7}, {%8,%9}, {%0,%1,%2,%3};"
        : "+f"(c[0]), "+f"(c[1]), "+f"(c[2]), "+f"(c[3])
        : "r"(a0), "r"(a1), "r"(a2), "r"(a3), "r"(b0), "r"(b1));
}

__device__ __forceinline__ uint16_t bf_bits(__nv_bfloat16 h) {
    uint16_t b;
    memcpy(&b, &h, 2);
    return b;
}

__device__ __forceinline__ void split_bf16(float v, uint16_t& hb, uint16_t& lb) {
    __nv_bfloat16 h = __float2bfloat16(v);
    float hf = __bfloat162float(h);
    __nv_bfloat16 l = __float2bfloat16(v - hf);
    hb = bf_bits(h);
    lb = bf_bits(l);
}

// ------------------------------ merged convert + weight prep ---------------
__global__ void conv_prep(const float* __restrict__ x0, const float* __restrict__ x1,
                          const float* __restrict__ x2,
                          const float* __restrict__ fcw0, const float* __restrict__ fcw1,
                          const float* __restrict__ fcw2, const float* __restrict__ W0,
                          const float* __restrict__ W1, const float* __restrict__ resW1,
                          const float* __restrict__ W2, const float* __restrict__ resW2) {
    const int S0 = N0 * 128, S1 = N1 * 256, S2 = N2 * 64;
    const int SX = S0 + S1 + S2;
    const int TOT = SX + W_TOTAL;
    for (int i = blockIdx.x * blockDim.x + threadIdx.x; i < TOT;
         i += gridDim.x * blockDim.x) {
        if (i < SX) {
            float v;
            uint16_t *ph, *pl;
            int j;
            if (i < S0)           { j = i;           v = x0[j]; ph = g_x0h; pl = g_x0l; }
            else if (i < S0 + S1) { j = i - S0;      v = x1[j]; ph = g_x1h; pl = g_x1l; }
            else                  { j = i - S0 - S1; v = x2[j]; ph = g_x2h; pl = g_x2l; }
            uint16_t hb, lb;
            split_bf16(v, hb, lb);
            ph[j] = hb;
            pl[j] = lb;
        } else {
            int idx = i - SX;
            int N, base, rel;
            int mode = 0;
            const float* src = nullptr;
            if (idx < 8192)        { src = fcw0; N = 64;  base = OFF_FCW0; rel = idx; }
            else if (idx < 24576)  { src = fcw1; N = 64;  base = OFF_FCW1; rel = idx - 8192; }
            else if (idx < 28672)  { src = fcw2; N = 64;  base = OFF_FCW2; rel = idx - 24576; }
            else if (idx < 45056)  { src = W0;   N = 256; base = OFF_W0;   rel = idx - 28672; }
            else if (idx < 176128) { N = 512; base = OFF_W1C;  rel = idx - 45056; mode = 1; }
            else                   { N = 32;  base = OFF_BCAT; rel = idx - 176128; mode = 2; }
            int k = rel / N, n = rel - k * N;
            float v;
            if (mode == 1)      v = (n < 256) ? W1[k * 256 + n] : resW1[k * 256 + (n - 256)];
            else if (mode == 2) v = (n < 16) ? W2[k * 16 + n] : resW2[k * 16 + (n - 16)];
            else                v = src[rel];
            uint16_t hb, lb;
            split_bf16(v, hb, lb);
            int c = k >> 5, kp = (k & 31) >> 1;
            size_t word = (size_t)c * (N * 16) + (size_t)n * 16 + kp;
            g_wh[base + word * 2 + (k & 1)] = hb;
            g_wl[base + word * 2 + (k & 1)] = lb;
        }
    }
}

// ------------------------------ big GEMM: 256 thr, BN=128, 2 CTA/SM --------
template <bool EL>
__global__ void __launch_bounds__(256, 2) gemm_cp2(
    const uint16_t* __restrict__ AhG, const uint16_t* __restrict__ AlG,
    const uint16_t* __restrict__ BhG, const uint16_t* __restrict__ BlG,
    float* __restrict__ C,
    const float* __restrict__ al, const float* __restrict__ ar,
    float* __restrict__ elp, float* __restrict__ erp,
    int M, int Ntot, int K, int ldc) {
    constexpr int NT = 8;
    constexpr int BN = 128;
    constexpr int PAD = 20;
    constexpr int A_PLANE = 128 * PAD * 4;
    constexpr int B_PLANE = BN * PAD * 4;
    constexpr int OFF_AL2 = A_PLANE;
    constexpr int OFF_BH2 = 2 * A_PLANE;
    constexpr int OFF_BL2 = 2 * A_PLANE + B_PLANE;
    constexpr int STAGE = 2 * A_PLANE + 2 * B_PLANE;
    extern __shared__ char smem[];

    int row0 = blockIdx.y * 128, col0 = blockIdx.x * BN;
    uint32_t sb = smem_u32(smem);
    int tid = threadIdx.x, wid = tid >> 5, lane = tid & 31;
    int g = lane >> 2, tig = lane & 3;
    int warpM = wid & 3, warpN = wid >> 2;

    float acc[2][NT][4];
    #pragma unroll
    for (int mt = 0; mt < 2; mt++)
        #pragma unroll
        for (int nt = 0; nt < NT; nt++)
            #pragma unroll
            for (int j = 0; j < 4; j++) acc[mt][nt][j] = 0.f;

    auto load_stage = [&](int s, int kt) {
        uint32_t base = sb + s * STAGE;
        #pragma unroll
        for (int i = 0; i < 2; i++) {
            int lin = tid + i * 256;
            int r = lin >> 2, c4 = lin & 3;
            int gr = row0 + r;
            int sz = (gr < M) ? 16 : 0;
            size_t boff = ((size_t)gr * K + kt * 32) * 2 + c4 * 16;
            cp16(base + (r * PAD + c4 * 4) * 4, (const char*)AhG + boff, sz);
            cp16(base + OFF_AL2 + (r * PAD + c4 * 4) * 4, (const char*)AlG + boff, sz);
        }
        #pragma unroll
        for (int i = 0; i < 2; i++) {
            int lin = tid + i * 256;
            int n = lin >> 2, c4 = lin & 3;
            size_t boff = ((size_t)kt * Ntot * 16 + (size_t)(col0 + n) * 16) * 4 + c4 * 16;
            cp16(base + OFF_BH2 + (n * PAD + c4 * 4) * 4, (const char*)BhG + boff, 16);
            cp16(base + OFF_BL2 + (n * PAD + c4 * 4) * 4, (const char*)BlG + boff, 16);
        }
    };

    uint32_t a_base = (uint32_t)((warpM * 32 + (lane & 15)) * PAD +
                                 ((lane & 16) ? 4 : 0)) * 4;
    uint32_t b_base = (uint32_t)((warpN * 64 + (lane & 7) +
                                  ((lane & 16) ? 8 : 0)) * PAD +
                                 ((lane & 8) ? 4 : 0)) * 4;

    int nk = K >> 5;
    load_stage(0, 0);
    CP_COMMIT();
    load_stage(1, 1);
    CP_COMMIT();

    for (int kt = 0; kt < nk; kt++) {
        CP_WAIT1();
        __syncthreads();
        int s = kt & 1;
        uint32_t sA  = sb + s * STAGE;
        uint32_t sAl = sA + OFF_AL2;
        uint32_t sBh = sA + OFF_BH2;
        uint32_t sBl = sA + OFF_BL2;

        #pragma unroll
        for (int kh = 0; kh < 2; kh++) {
            uint32_t ko = kh * 32;
            uint32_t aH[2][4], aL[2][4];
            #pragma unroll
            for (int mt = 0; mt < 2; mt++) {
                LDSM_X4(aH[mt], sA + a_base + mt * 16 * PAD * 4 + ko);
                LDSM_X4(aL[mt], sAl + a_base + mt * 16 * PAD * 4 + ko);
            }
            #pragma unroll
            for (int nt2 = 0; nt2 < NT / 2; nt2++) {
                uint32_t bh[4], bl[4];
                LDSM_X4(bh, sBh + b_base + nt2 * 16 * PAD * 4 + ko);
                LDSM_X4(bl, sBl + b_base + nt2 * 16 * PAD * 4 + ko);
                #pragma unroll
                for (int half = 0; half < 2; half++) {
                    int nt = nt2 * 2 + half;
                    uint32_t bh0 = bh[half * 2], bh1 = bh[half * 2 + 1];
                    uint32_t bl0 = bl[half * 2], bl1 = bl[half * 2 + 1];
                    #pragma unroll
                    for (int mt = 0; mt < 2; mt++) {
                        mma_bf16(acc[mt][nt], aH[mt][0], aH[mt][1], aH[mt][2], aH[mt][3], bh0, bh1);
                        mma_bf16(acc[mt][nt], aL[mt][0], aL[mt][1], aL[mt][2], aL[mt][3], bh0, bh1);
                        mma_bf16(acc[mt][nt], aH[mt][0], aH[mt][1], aH[mt][2], aH[mt][3], bl0, bl1);
                    }
                }
            }
        }
        __syncthreads();
        if (kt + 2 < nk) load_stage(s, kt + 2);
        CP_COMMIT();
    }

    #pragma unroll
    for (int mt = 0; mt < 2; mt++) {
        #pragma unroll
        for (int nt = 0; nt < NT; nt++) {
            int r0 = row0 + warpM * 32 + mt * 16 + g;
            int c = col0 + warpN * 64 + nt * 8 + tig * 2;
            #pragma unroll
            for (int half = 0; half < 2; half++) {
                int r = r0 + half * 8;
                if (r >= M) continue;
                *(float2*)&C[(size_t)r * ldc + c] =
                    make_float2(acc[mt][nt][half * 2 + 0], acc[mt][nt][half * 2 + 1]);
            }
        }
    }

    if (EL && col0 < 256) {
        float elacc[2][2][2], eracc[2][2][2];
        #pragma unroll
        for (int mt = 0; mt < 2; mt++)
            #pragma unroll
            for (int half = 0; half < 2; half++)
                #pragma unroll
                for (int hl = 0; hl < 2; hl++) {
                    elacc[mt][half][hl] = 0.f;
                    eracc[mt][half][hl] = 0.f;
                }
        #pragma unroll
        for (int nt = 0; nt < NT; nt++) {
            int hl = nt >> 2;
            int h = (col0 >> 5) + warpN * 2 + hl;
            int o = (nt * 8 + tig * 2) & 31;
            float al0v = al[h * 32 + o], al1v = al[h * 32 + o + 1];
            float ar0v = ar[h * 32 + o], ar1v = ar[h * 32 + o + 1];
            #pragma unroll
            for (int mt = 0; mt < 2; mt++)
                #pragma unroll
                for (int half = 0; half < 2; half++) {
                    float v0 = acc[mt][nt][half * 2 + 0];
                    float v1 = acc[mt][nt][half * 2 + 1];
                    elacc[mt][half][hl] += v0 * al0v + v1 * al1v;
                    eracc[mt][half][hl] += v0 * ar0v + v1 * ar1v;
                }
        }
        #pragma unroll
        for (int mt = 0; mt < 2; mt++)
            #pragma unroll
            for (int half = 0; half < 2; half++)
                #pragma unroll
                for (int hl = 0; hl < 2; hl++) {
                    float ev = elacc[mt][half][hl];
                    float rv = eracc[mt][half][hl];
                    ev += __shfl_xor_sync(0xffffffffu, ev, 1);
                    ev += __shfl_xor_sync(0xffffffffu, ev, 2);
                    rv += __shfl_xor_sync(0xffffffffu, rv, 1);
                    rv += __shfl_xor_sync(0xffffffffu, rv, 2);
                    if (tig == 0) {
                        int r = row0 + warpM * 32 + mt * 16 + g + half * 8;
                        int h2 = (col0 >> 5) + warpN * 2 + hl;
                        if (r < M) {
                            elp[r * 8 + h2] = ev;
                            erp[r * 8 + h2] = rv;
                        }
                    }
                }
    }
}

// ------------------------------ proj GEMM: 256 thr, BN=64, 2 CTA/SM --------
// C planes (bf16 hi/lo) = A @ B + bias. 8 warps (4M x 2N), warp tile 32x32.
__device__ __forceinline__ void proj_body2(
    const uint16_t* __restrict__ AhG, const uint16_t* __restrict__ AlG,
    const uint16_t* __restrict__ BhG, const uint16_t* __restrict__ BlG,
    const float* __restrict__ bias, uint16_t* __restrict__ Ch,
    uint16_t* __restrict__ Cl, int M, int K, int row0, char* smem) {
    constexpr int NT = 4;
    constexpr int BN = 64;
    constexpr int PAD = 20;
    constexpr int A_PLANE = 128 * PAD * 4;
    constexpr int B_PLANE = BN * PAD * 4;
    constexpr int OFF_AL2 = A_PLANE;
    constexpr int OFF_BH2 = 2 * A_PLANE;
    constexpr int OFF_BL2 = 2 * A_PLANE + B_PLANE;
    constexpr int STAGE = 2 * A_PLANE + 2 * B_PLANE;

    uint32_t sb = smem_u32(smem);
    int tid = threadIdx.x, wid = tid >> 5, lane = tid & 31;
    int g = lane >> 2, tig = lane & 3;
    int warpM = wid & 3, warpN = wid >> 2;

    float acc[2][NT][4];
    #pragma unroll
    for (int mt = 0; mt < 2; mt++)
        #pragma unroll
        for (int nt = 0; nt < NT; nt++)
            #pragma unroll
            for (int j = 0; j < 4; j++) acc[mt][nt][j] = 0.f;

    auto load_stage = [&](int s, int kt) {
        uint32_t base = sb + s * STAGE;
        #pragma unroll
        for (int i = 0; i < 2; i++) {
            int lin = tid + i * 256;
            int r = lin >> 2, c4 = lin & 3;
            int gr = row0 + r;
            int sz = (gr < M) ? 16 : 0;
            size_t boff = ((size_t)gr * K + kt * 32) * 2 + c4 * 16;
            cp16(base + (r * PAD + c4 * 4) * 4, (const char*)AhG + boff, sz);
            cp16(base + OFF_AL2 + (r * PAD + c4 * 4) * 4, (const char*)AlG + boff, sz);
        }
        if (tid < BN * 4) {
            int n = tid >> 2, c4 = tid & 3;
            size_t boff = ((size_t)kt * 64 * 16 + (size_t)n * 16) * 4 + c4 * 16;
            cp16(base + OFF_BH2 + (n * PAD + c4 * 4) * 4, (const char*)BhG + boff, 16);
            cp16(base + OFF_BL2 + (n * PAD + c4 * 4) * 4, (const char*)BlG + boff, 16);
        }
    };

    uint32_t a_base = (uint32_t)((warpM * 32 + (lane & 15)) * PAD +
                                 ((lane & 16) ? 4 : 0)) * 4;
    uint32_t b_base = (uint32_t)((warpN * 32 + (lane & 7) +
                                  ((lane & 16) ? 8 : 0)) * PAD +
                                 ((lane & 8) ? 4 : 0)) * 4;

    int nk = K >> 5;
    load_stage(0, 0);
    CP_COMMIT();
    load_stage(1, 1 < nk ? 1 : 0);
    CP_COMMIT();

    for (int kt = 0; kt < nk; kt++) {
        CP_WAIT1();
        __syncthreads();
        int s = kt & 1;
        uint32_t sA  = sb + s * STAGE;
        uint32_t sAl = sA + OFF_AL2;
        uint32_t sBh = sA + OFF_BH2;
        uint32_t sBl = sA + OFF_BL2;

        #pragma unroll
        for (int kh = 0; kh < 2; kh++) {
            uint32_t ko = kh * 32;
            uint32_t aH[2][4], aL[2][4];
            #pragma unroll
            for (int mt = 0; mt < 2; mt++) {
                LDSM_X4(aH[mt], sA + a_base + mt * 16 * PAD * 4 + ko);
                LDSM_X4(aL[mt], sAl + a_base + mt * 16 * PAD * 4 + ko);
            }
            #pragma unroll
            for (int nt2 = 0; nt2 < NT / 2; nt2++) {
                uint32_t bh[4], bl[4];
                LDSM_X4(bh, sBh + b_base + nt2 * 16 * PAD * 4 + ko);
                LDSM_X4(bl, sBl + b_base + nt2 * 16 * PAD * 4 + ko);
                #pragma unroll
                for (int half = 0; half < 2; half++) {
                    int nt = nt2 * 2 + half;
                    uint32_t bh0 = bh[half * 2], bh1 = bh[half * 2 + 1];
                    uint32_t bl0 = bl[half * 2], bl1 = bl[half * 2 + 1];
                    #pragma unroll
                    for (int mt = 0; mt < 2; mt++) {
                        mma_bf16(acc[mt][nt], aH[mt][0], aH[mt][1], aH[mt][2], aH[mt][3], bh0, bh1);
                        mma_bf16(acc[mt][nt], aL[mt][0], aL[mt][1], aL[mt][2], aL[mt][3], bh0, bh1);
                        mma_bf16(acc[mt][nt], aH[mt][0], aH[mt][1], aH[mt][2], aH[mt][3], bl0, bl1);
                    }
                }
            }
        }
        __syncthreads();
        if (kt + 2 < nk) load_stage(s, kt + 2);
        CP_COMMIT();
    }

    #pragma unroll
    for (int mt = 0; mt < 2; mt++) {
        #pragma unroll
        for (int nt = 0; nt < NT; nt++) {
            int r0 = row0 + warpM * 32 + mt * 16 + g;
            int c = warpN * 32 + nt * 8 + tig * 2;
            float b0a = bias[c], b1a = bias[c + 1];
            #pragma unroll
            for (int half = 0; half < 2; half++) {
                int r = r0 + half * 8;
                if (r >= M) continue;
                float v0 = acc[mt][nt][half * 2 + 0] + b0a;
                float v1 = acc[mt][nt][half * 2 + 1] + b1a;
                uint16_t h0b, l0b, h1b, l1b;
                split_bf16(v0, h0b, l0b);
                split_bf16(v1, h1b, l1b);
                *(uint32_t*)&Ch[(size_t)r * 64 + c] = (uint32_t)h0b | ((uint32_t)h1b << 16);
                *(uint32_t*)&Cl[(size_t)r * 64 + c] = (uint32_t)l0b | ((uint32_t)l1b << 16);
            }
        }
    }
}

__global__ void __launch_bounds__(256, 2) proj_cp2(const float* __restrict__ fcb0,
                                                   const float* __restrict__ fcb1,
                                                   const float* __restrict__ fcb2) {
    extern __shared__ char smem[];
    const int NB0 = (N0 + 127) / 128;
    const int NB01 = NB0 + (N1 + 127) / 128;
    int by = blockIdx.y;
    if (by < NB0) {
        proj_body2(g_x0h, g_x0l, g_wh + OFF_FCW0, g_wl + OFF_FCW0, fcb0,
                   g_h0h, g_h0l, N0, 128, by * 128, smem);
    } else if (by < NB01) {
        proj_body2(g_x1h, g_x1l, g_wh + OFF_FCW1, g_wl + OFF_FCW1, fcb1,
                   g_h0h + (size_t)N0 * 64, g_h0l + (size_t)N0 * 64,
                   N1, 256, (by - NB0) * 128, smem);
    } else {
        proj_body2(g_x2h, g_x2l, g_wh + OFF_FCW2, g_wl + OFF_FCW2, fcb2,
                   g_h0h + (size_t)(N0 + N1) * 64, g_h0l + (size_t)(N0 + N1) * 64,
                   N2, 64, (by - NB01) * 128, smem);
    }
}

// ------------------------------ small GEMM (512 thr, layer 2) --------------
template <int NT, int ELMODE>
__global__ void __launch_bounds__(512) gemm_cp(
    const uint16_t* __restrict__ AhG, const uint16_t* __restrict__ AlG,
    const uint16_t* __restrict__ BhG, const uint16_t* __restrict__ BlG,
    float* __restrict__ C,
    const float* __restrict__ al, const float* __restrict__ ar,
    float* __restrict__ elp, float* __restrict__ erp,
    int M, int Ntot, int K, int ldc) {
    constexpr int BN = NT * 32;
    constexpr int PAD = 20;
    constexpr int A_PLANE = 128 * PAD * 4;
    constexpr int B_PLANE = BN * PAD * 4;
    constexpr int OFF_AL2 = A_PLANE;
    constexpr int OFF_BH2 = 2 * A_PLANE;
    constexpr int OFF_BL2 = 2 * A_PLANE + B_PLANE;
    constexpr int STAGE = 2 * A_PLANE + 2 * B_PLANE;
    extern __shared__ char smem[];

    int row0 = blockIdx.y * 128, col0 = blockIdx.x * BN;
    uint32_t sb = smem_u32(smem);
    int tid = threadIdx.x, wid = tid >> 5, lane = tid & 31;
    int g = lane >> 2, tig = lane & 3;
    int warpM = wid & 3, warpN = wid >> 2;

    float acc[2][NT][4];
    #pragma unroll
    for (int mt = 0; mt < 2; mt++)
        #pragma unroll
        for (int nt = 0; nt < NT; nt++)
            #pragma unroll
            for (int j = 0; j < 4; j++) acc[mt][nt][j] = 0.f;

    auto load_stage = [&](int s, int kt) {
        uint32_t base = sb + s * STAGE;
        {
            int r = tid >> 2, c4 = tid & 3;
            int gr = row0 + r;
            int sz = (gr < M) ? 16 : 0;
            size_t boff = ((size_t)gr * K + kt * 32) * 2 + c4 * 16;
            cp16(base + (r * PAD + c4 * 4) * 4, (const char*)AhG + boff, sz);
            cp16(base + OFF_AL2 + (r * PAD + c4 * 4) * 4, (const char*)AlG + boff, sz);
        }
        #pragma unroll
        for (int lin = tid; lin < BN * 4; lin += 512) {
            int n = lin >> 2, c4 = lin & 3;
            size_t boff = ((size_t)kt * Ntot * 16 + (size_t)(col0 + n) * 16) * 4 + c4 * 16;
            cp16(base + OFF_BH2 + (n * PAD + c4 * 4) * 4, (const char*)BhG + boff, 16);
            cp16(base + OFF_BL2 + (n * PAD + c4 * 4) * 4, (const char*)BlG + boff, 16);
        }
    };

    uint32_t a_base = (uint32_t)((warpM * 32 + (lane & 15)) * PAD +
                                 ((lane & 16) ? 4 : 0)) * 4;

    int nk = K >> 5;
    load_stage(0, 0);
    CP_COMMIT();
    load_stage(1, 1);
    CP_COMMIT();

    for (int kt = 0; kt < nk; kt++) {
        CP_WAIT1();
        __syncthreads();
        if (kt + 2 < nk) load_stage((kt + 2) % 3, kt + 2);
        CP_COMMIT();
        int s = kt % 3;
        uint32_t sA  = sb + s * STAGE;
        uint32_t sAl = sA + OFF_AL2;

        #pragma unroll
        for (int kh = 0; kh < 2; kh++) {
            uint32_t ko = kh * 32;
            uint32_t aH[2][4], aL[2][4];
            #pragma unroll
            for (int mt = 0; mt < 2; mt++) {
                LDSM_X4(aH[mt], sA + a_base + mt * 16 * PAD * 4 + ko);
                LDSM_X4(aL[mt], sAl + a_base + mt * 16 * PAD * 4 + ko);
            }
            const uint32_t* BsH = (const uint32_t*)(smem + s * STAGE + OFF_BH2);
            const uint32_t* BsL = (const uint32_t*)(smem + s * STAGE + OFF_BL2);
            int kp0 = kh * 8;
            int n0 = warpN * 8;
            int bbase = (n0 + g) * PAD + kp0 + tig;
            uint32_t bh0 = BsH[bbase], bh1 = BsH[bbase + 4];
            uint32_t bl0 = BsL[bbase], bl1 = BsL[bbase + 4];
            #pragma unroll
            for (int mt = 0; mt < 2; mt++) {
                mma_bf16(acc[mt][0], aH[mt][0], aH[mt][1], aH[mt][2], aH[mt][3], bh0, bh1);
                mma_bf16(acc[mt][0], aL[mt][0], aL[mt][1], aL[mt][2], aL[mt][3], bh0, bh1);
                mma_bf16(acc[mt][0], aH[mt][0], aH[mt][1], aH[mt][2], aH[mt][3], bl0, bl1);
            }
        }
        __syncthreads();
    }

    #pragma unroll
    for (int mt = 0; mt < 2; mt++) {
        int r0 = row0 + warpM * 32 + mt * 16 + g;
        int c = col0 + warpN * 8 + tig * 2;
        #pragma unroll
        for (int half = 0; half < 2; half++) {
            int r = r0 + half * 8;
            if (r >= M) continue;
            *(float2*)&C[(size_t)r * ldc + c] =
                make_float2(acc[mt][0][half * 2 + 0], acc[mt][0][half * 2 + 1]);
        }
    }

    if (ELMODE == 2) {
        float evp[2][2], rvp[2][2];
        #pragma unroll
        for (int mt = 0; mt < 2; mt++)
            #pragma unroll
            for (int half = 0; half < 2; half++) {
                evp[mt][half] = 0.f;
                rvp[mt][half] = 0.f;
            }
        if (warpN < 2) {
            #pragma unroll
            for (int mt = 0; mt < 2; mt++)
                #pragma unroll
                for (int half = 0; half < 2; half++) {
                    int c = warpN * 8 + tig * 2;
                    float v0 = acc[mt][0][half * 2 + 0];
                    float v1 = acc[mt][0][half * 2 + 1];
                    float ev = v0 * al[c] + v1 * al[c + 1];
                    float rv = v0 * ar[c] + v1 * ar[c + 1];
                    ev += __shfl_xor_sync(0xffffffffu, ev, 1);
                    ev += __shfl_xor_sync(0xffffffffu, ev, 2);
                    rv += __shfl_xor_sync(0xffffffffu, rv, 1);
                    rv += __shfl_xor_sync(0xffffffffu, rv, 2);
                    evp[mt][half] = ev;
                    rvp[mt][half] = rv;
                }
        }
        float* buf = (float*)smem;
        __syncthreads();
        if (warpN == 1 && tig == 0) {
            #pragma unroll
            for (int mt = 0; mt < 2; mt++)
                #pragma unroll
                for (int half = 0; half < 2; half++) {
                    int rr = warpM * 32 + mt * 16 + g + half * 8;
                    buf[rr * 2 + 0] = evp[mt][half];
                    buf[rr * 2 + 1] = rvp[mt][half];
                }
        }
        __syncthreads();
        if (warpN == 0 && tig == 0) {
            #pragma unroll
            for (int mt = 0; mt < 2; mt++)
                #pragma unroll
                for (int half = 0; half < 2; half++) {
                    int rr = warpM * 32 + mt * 16 + g + half * 8;
                    int r = row0 + rr;
                    if (r < M) {
                        elp[r] = evp[mt][half] + buf[rr * 2 + 0];
                        erp[r] = rvp[mt][half] + buf[rr * 2 + 1];
                    }
                }
        }
    }
}

// ------------------------------ CSR build ----------------------------------
__global__ void hist_kernel(const int* __restrict__ dst) {
    int e = blockIdx.x * blockDim.x + threadIdx.x;
    if (e < N_EDGES) atomicAdd(&g_cnt[dst[e]], 1);
}

__global__ void scan_block_kernel() {
    __shared__ int sh[SCAN_B];
    int t = threadIdx.x;
    int i = blockIdx.x * SCAN_B + t;
    int v = (i < N_NODES) ? g_cnt[i] : 0;
    sh[t] = v;
    __syncthreads();
    #pragma unroll
    for (int off = 1; off < SCAN_B; off <<= 1) {
        int tmp = (t >= off) ? sh[t - off] : 0;
        __syncthreads();
        sh[t] += tmp;
        __syncthreads();
    }
    if (i < N_NODES) g_rowptr[i + 1] = sh[t];
    if (t == SCAN_B - 1) g_bsum[blockIdx.x] = sh[t];
}

__global__ void scan_top_kernel() {
    __shared__ int sh[128];
    int t = threadIdx.x;
    int v = (t < SCAN_NB) ? g_bsum[t] : 0;
    sh[t] = v;
    __syncthreads();
    #pragma unroll
    for (int off = 1; off < 128; off <<= 1) {
        int tmp = (t >= off) ? sh[t - off] : 0;
        __syncthreads();
        sh[t] += tmp;
        __syncthreads();
    }
    if (t < SCAN_NB) g_boff[t] = sh[t] - v;
}

__global__ void scan_add_kernel() {
    int t = threadIdx.x;
    int i = blockIdx.x * SCAN_B + t;
    if (i < N_NODES) {
        int v = g_rowptr[i + 1] + g_boff[blockIdx.x];
        g_rowptr[i + 1] = v;
        g_cursor[i] = v - g_cnt[i];
    }
    if (i == 0) g_rowptr[0] = 0;
}

__global__ void scatter_kernel(const int* __restrict__ src, const int* __restrict__ dst,
                               const int* __restrict__ et) {
    int e = blockIdx.x * blockDim.x + threadIdx.x;
    if (e >= N_EDGES) return;
    int d = dst[e];
    int pos = atomicAdd(&g_cursor[d], 1);
    g_srcS[pos] = src[e];
    g_etS[pos]  = et[e];
}

// ------------------------------ edge-type attention ------------------------
__global__ void etype_att_kernel(const float* __restrict__ eemb, const float* __restrict__ We,
                                 const float* __restrict__ ae, float* __restrict__ out, int H) {
    int t = blockIdx.x / H;
    int h = blockIdx.x % H;
    int d = threadIdx.x;
    int Wcols = H * 64;
    float v = 0.f;
    #pragma unroll 4
    for (int k = 0; k < 64; k++)
        v += eemb[t * 64 + k] * We[k * Wcols + h * 64 + d];
    v *= ae[h * 64 + d];
    __shared__ float sh[64];
    sh[d] = v;
    __syncthreads();
    #pragma unroll
    for (int o = 32; o > 0; o >>= 1) {
        if (d < o) sh[d] += sh[d + o];
        __syncthreads();
    }
    if (d == 0) out[t * H + h] = sh[0];
}

// ------------------------------ fused GAT edge kernel (H=8, pipelined) -----
template <bool BLEND, bool SAVE_A, bool RES>
__global__ void fused_gat8(const float* __restrict__ feat, const float* __restrict__ el,
                           const float* __restrict__ er, const float* __restrict__ etatt,
                           float* __restrict__ a0,
                           uint16_t* __restrict__ outh, uint16_t* __restrict__ outl) {
    int warp = (blockIdx.x * blockDim.x + threadIdx.x) >> 5;
    int lane = threadIdx.x & 31;
    if (warp >= N_NODES) return;
    int n = warp;
    int h = lane & 7, eslot = lane >> 3;
    float er_n = er[n * 8 + h];
    float eat[6];
    #pragma unroll
    for (int t = 0; t < 6; t++) eat[t] = etatt[t * 8 + h];
    int b = g_rowptr[n], e = g_rowptr[n + 1];

    // ---- pass 1: online softmax, 2-deep pipelined index chain ----
    float m = -1e30f, s = 0.f;
    {
        int i1 = b + eslot;
        int sA = (i1 < e) ? g_srcS[i1] : 0;
        int tA = (i1 < e) ? g_etS[i1] : 0;
        float eA = (i1 < e) ? el[sA * 8 + h] : 0.f;
        int i2 = i1 + 4;
        int sB = (i2 < e) ? g_srcS[i2] : 0;
        int tB = (i2 < e) ? g_etS[i2] : 0;
        for (int i0 = b; i0 < e; i0 += 4) {
            float eB = (i0 + 4 + eslot < e) ? el[sB * 8 + h] : 0.f;
            int i3 = i0 + 8 + eslot;
            int sC = (i3 < e) ? g_srcS[i3] : 0;
            int tC = (i3 < e) ? g_etS[i3] : 0;
            if (i0 + eslot < e) {
                float ev = eA + er_n + eat[tA];
                ev = (ev > 0.f) ? ev : 0.2f * ev;
                float nm = fmaxf(m, ev);
                s = s * __expf(m - nm) + __expf(ev - nm);
                m = nm;
            }
            sA = sB; tA = tB; eA = eB;
            sB = sC; tB = tC;
        }
    }
    #pragma unroll
    for (int off = 8; off <= 16; off <<= 1) {
        float om = __shfl_xor_sync(0xffffffffu, m, off);
        float os = __shfl_xor_sync(0xffffffffu, s, off);
        float nm = fmaxf(m, om);
        s = s * __expf(m - nm) + os * __expf(om - nm);
        m = nm;
    }

    float acc[8];
    #pragma unroll
    for (int h2 = 0; h2 < 8; h2++)
        acc[h2] = RES ? feat[(size_t)n * 512 + 256 + h2 * 32 + lane] : 0.f;

    // ---- pass 2: aggregation, same 2-deep pipeline on the index chain ----
    int i1 = b + eslot;
    int sA = (i1 < e) ? g_srcS[i1] : 0;
    int tA = (i1 < e) ? g_etS[i1] : 0;
    float eA = (i1 < e) ? el[sA * 8 + h] : 0.f;
    int i2 = i1 + 4;
    int sB = (i2 < e) ? g_srcS[i2] : 0;
    int tB = (i2 < e) ? g_etS[i2] : 0;

    int i0 = b;
    for (; i0 + 4 <= e; i0 += 4) {
        float eB = (i0 + 4 + eslot < e) ? el[sB * 8 + h] : 0.f;
        int i3 = i0 + 8 + eslot;
        int sC = (i3 < e) ? g_srcS[i3] : 0;
        int tC = (i3 < e) ? g_etS[i3] : 0;

        int i = i0 + eslot;
        float ev = eA + er_n + eat[tA];
        ev = (ev > 0.f) ? ev : 0.2f * ev;
        float a = __expf(ev - m) / s;
        if (BLEND) a = a * 0.95f + 0.05f * a0[(size_t)i * 8 + h];
        if (SAVE_A) a0[(size_t)i * 8 + h] = a;

        int s2[4];
        #pragma unroll
        for (int e2 = 0; e2 < 4; e2++)
            s2[e2] = __shfl_sync(0xffffffffu, sA, e2 * 8);
        float tmp[4][8];
        #pragma unroll
        for (int e2 = 0; e2 < 4; e2++) {
            const float* f = feat + (size_t)s2[e2] * 512;
            #pragma unroll
            for (int h2 = 0; h2 < 8; h2++)
                tmp[e2][h2] = f[h2 * 32 + lane];
        }
        #pragma unroll
        for (int e2 = 0; e2 < 4; e2++)
            #pragma unroll
            for (int h2 = 0; h2 < 8; h2++) {
                float ah = __shfl_sync(0xffffffffu, a, e2 * 8 + h2);
                acc[h2] += ah * tmp[e2][h2];
            }

        sA = sB; tA = tB; eA = eB;
        sB = sC; tB = tC;
    }
    if (i0 < e) {
        int i = i0 + eslot;
        float a = 0.f;
        if (i < e) {
            float ev = eA + er_n + eat[tA];
            ev = (ev > 0.f) ? ev : 0.2f * ev;
            a = __expf(ev - m) / s;
            if (BLEND) a = a * 0.95f + 0.05f * a0[(size_t)i * 8 + h];
            if (SAVE_A) a0[(size_t)i * 8 + h] = a;
        }
        #pragma unroll
        for (int e2 = 0; e2 < 4; e2++) {
            if (i0 + e2 < e) {
                int s2 = __shfl_sync(0xffffffffu, sA, e2 * 8);
                const float* f = feat + (size_t)s2 * 512;
                #pragma unroll
                for (int h2 = 0; h2 < 8; h2++) {
                    float ah = __shfl_sync(0xffffffffu, a, e2 * 8 + h2);
                    acc[h2] += ah * f[h2 * 32 + lane];
                }
            }
        }
    }

    #pragma unroll
    for (int h2 = 0; h2 < 8; h2++) {
        float v = acc[h2];
        v = (v > 0.f) ? v : expm1f(v);
        uint16_t hb, lb;
        split_bf16(v, hb, lb);
        outh[(size_t)n * 256 + h2 * 32 + lane] = hb;
        outl[(size_t)n * 256 + h2 * 32 + lane] = lb;
    }
}

// ------------------------------ fused GAT edge kernel (H=1, out 16) --------
__global__ void fused_gat1(const float* __restrict__ f2, const float* __restrict__ el,
                           const float* __restrict__ er, const float* __restrict__ etatt,
                           float* __restrict__ out) {
    int warp = (blockIdx.x * blockDim.x + threadIdx.x) >> 5;
    int lane = threadIdx.x & 31;
    if (warp >= N_NODES) return;
    int n = warp;
    int eslot = lane >> 4;
    int sub = lane & 15;
    float er_n = er[n];
    float eat[6];
    #pragma unroll
    for (int t = 0; t < 6; t++) eat[t] = etatt[t];
    int b = g_rowptr[n], e = g_rowptr[n + 1];

    float m = -1e30f, s = 0.f;
    for (int i0 = b; i0 < e; i0 += 32) {
        int i = i0 + lane;
        if (i < e) {
            float ev = el[g_srcS[i]] + er_n + eat[g_etS[i]];
            ev = (ev > 0.f) ? ev : 0.2f * ev;
            float nm = fmaxf(m, ev);
            s = s * __expf(m - nm) + __expf(ev - nm);
            m = nm;
        }
    }
    #pragma unroll
    for (int off = 16; off > 0; off >>= 1) {
        float om = __shfl_xor_sync(0xffffffffu, m, off);
        float os = __shfl_xor_sync(0xffffffffu, s, off);
        float nm = fmaxf(m, om);
        s = s * __expf(m - nm) + os * __expf(om - nm);
        m = nm;
    }

    float acc = (eslot == 0) ? f2[(size_t)n * 32 + 16 + sub] : 0.f;
    int i0 = b;
    for (; i0 + 2 <= e; i0 += 2) {
        int i = i0 + eslot;
        int sidx = g_srcS[i];
        float ev = el[sidx] + er_n + eat[g_etS[i]];
        ev = (ev > 0.f) ? ev : 0.2f * ev;
        float a = __expf(ev - m) / s;
        acc += a * f2[(size_t)sidx * 32 + sub];
    }
    if (i0 < e) {
        if (eslot == 0) {
            int sidx = g_srcS[i0];
            float ev = el[sidx] + er_n + eat[g_etS[i0]];
            ev = (ev > 0.f) ? ev : 0.2f * ev;
            float a = __expf(ev - m) / s;
            acc += a * f2[(size_t)sidx * 32 + sub];
        }
    }
    acc += __shfl_down_sync(0xffffffffu, acc, 16);
    if (lane < 16) out[(size_t)n * 16 + lane] = acc;
}

// ---------------------------------------------------------------------------
static inline int cdiv(int a, int b) { return (a + b - 1) / b; }

extern "C" void kernel_launch(void* const* d_in, const int* in_sizes, int n_in,
                              void* d_out, int out_size) {
    const float* x0    = (const float*)d_in[0];
    const float* x1    = (const float*)d_in[1];
    const float* x2    = (const float*)d_in[2];
    const float* fcw0  = (const float*)d_in[3];
    const float* fcb0  = (const float*)d_in[4];
    const float* fcw1  = (const float*)d_in[5];
    const float* fcb1  = (const float*)d_in[6];
    const float* fcw2  = (const float*)d_in[7];
    const float* fcb2  = (const float*)d_in[8];
    const float* W0    = (const float*)d_in[9];
    const float* We0   = (const float*)d_in[10];
    const float* eemb0 = (const float*)d_in[11];
    const float* al0   = (const float*)d_in[12];
    const float* ar0   = (const float*)d_in[13];
    const float* ae0   = (const float*)d_in[14];
    const float* W1    = (const float*)d_in[15];
    const float* We1   = (const float*)d_in[16];
    const float* eemb1 = (const float*)d_in[17];
    const float* al1   = (const float*)d_in[18];
    const float* ar1   = (const float*)d_in[19];
    const float* ae1   = (const float*)d_in[20];
    const float* resW1 = (const float*)d_in[21];
    const float* W2    = (const float*)d_in[22];
    const float* We2   = (const float*)d_in[23];
    const float* eemb2 = (const float*)d_in[24];
    const float* al2   = (const float*)d_in[25];
    const float* ar2   = (const float*)d_in[26];
    const float* ae2   = (const float*)d_in[27];
    const float* resW2 = (const float*)d_in[28];
    const int*   src   = (const int*)d_in[29];
    const int*   dst   = (const int*)d_in[30];
    const int*   etype = (const int*)d_in[31];
    float* out = (float*)d_out;

    float *p_fr, *p_f2, *p_a0, *p_el, *p_er, *p_etatt;
    uint16_t *p_wh, *p_wl, *p_h0h, *p_h0l, *p_hAh, *p_hAl, *p_hBh, *p_hBl;
    int* p_cnt;
    cudaGetSymbolAddress((void**)&p_cnt, g_cnt);
    cudaGetSymbolAddress((void**)&p_fr, g_fr);
    cudaGetSymbolAddress((void**)&p_f2, g_f2);
    cudaGetSymbolAddress((void**)&p_a0, g_a0);
    cudaGetSymbolAddress((void**)&p_el, g_el);
    cudaGetSymbolAddress((void**)&p_er, g_er);
    cudaGetSymbolAddress((void**)&p_etatt, g_etatt);
    cudaGetSymbolAddress((void**)&p_wh, g_wh);
    cudaGetSymbolAddress((void**)&p_wl, g_wl);
    cudaGetSymbolAddress((void**)&p_h0h, g_h0h);
    cudaGetSymbolAddress((void**)&p_h0l, g_h0l);
    cudaGetSymbolAddress((void**)&p_hAh, g_hAh);
    cudaGetSymbolAddress((void**)&p_hAl, g_hAl);
    cudaGetSymbolAddress((void**)&p_hBh, g_hBh);
    cudaGetSymbolAddress((void**)&p_hBl, g_hBl);

    const int STG2 = 2 * (2 * (128 * 20 * 4) + 2 * (128 * 20 * 4));     // 81920
    const int STGP = 2 * (2 * (128 * 20 * 4) + 2 * (64 * 20 * 4));      // 61440
    const int STG1 = 3 * (2 * (128 * 20 * 4) + 2 * (32 * 20 * 4));      // 76800
    cudaFuncSetAttribute(gemm_cp2<true>, cudaFuncAttributeMaxDynamicSharedMemorySize, STG2);
    cudaFuncSetAttribute(proj_cp2, cudaFuncAttributeMaxDynamicSharedMemorySize, STGP);
    cudaFuncSetAttribute(gemm_cp<1, 2>, cudaFuncAttributeMaxDynamicSharedMemorySize, STG1);

    const int WB = cdiv(N_NODES * 32, 256);
    const int GY = cdiv(N_NODES, 128);
    const int PROJ_BLKS = cdiv(N0, 128) + cdiv(N1, 128) + cdiv(N2, 128);
    cudaStream_t s2 = g_sh.s;

    // ---- fork: CSR build + etype_att on side stream ----
    cudaEventRecord(g_sh.a, 0);
    cudaStreamWaitEvent(s2, g_sh.a, 0);
    cudaMemsetAsync(p_cnt, 0, N_NODES * sizeof(int), s2);

    // ---- main chain ----
    conv_prep<<<2048, 256>>>(x0, x1, x2, fcw0, fcw1, fcw2, W0, W1, resW1, W2, resW2);
    proj_cp2<<<dim3(1, PROJ_BLKS), 256, STGP>>>(fcb0, fcb1, fcb2);
    gemm_cp2<true><<<dim3(2, GY), 256, STG2>>>(
        p_h0h, p_h0l, p_wh + OFF_W0, p_wl + OFF_W0, p_fr,
        al0, ar0, p_el, p_er, N_NODES, 256, 64, 512);

    // ---- side stream: CSR build + edge-type attention ----
    hist_kernel<<<cdiv(N_EDGES, 256), 256, 0, s2>>>(dst);
    scan_block_kernel<<<SCAN_NB, SCAN_B, 0, s2>>>();
    scan_top_kernel<<<1, 128, 0, s2>>>();
    scan_add_kernel<<<SCAN_NB, SCAN_B, 0, s2>>>();
    scatter_kernel<<<cdiv(N_EDGES, 256), 256, 0, s2>>>(src, dst, etype);
    etype_att_kernel<<<6 * 8, 64, 0, s2>>>(eemb0, We0, ae0, p_etatt + 0, 8);
    etype_att_kernel<<<6 * 8, 64, 0, s2>>>(eemb1, We1, ae1, p_etatt + 48, 8);
    etype_att_kernel<<<6 * 1, 64, 0, s2>>>(eemb2, We2, ae2, p_etatt + 96, 1);
    cudaEventRecord(g_sh.b, s2);
    cudaStreamWaitEvent(0, g_sh.b, 0);

    // ---- layer 0 ----
    fused_gat8<false, true, false><<<WB, 256>>>(p_fr, p_el, p_er, p_etatt + 0,
                                                p_a0, p_hAh, p_hAl);

    // ---- layer 1 ----
    gemm_cp2<true><<<dim3(4, GY), 256, STG2>>>(
        p_hAh, p_hAl, p_wh + OFF_W1C, p_wl + OFF_W1C, p_fr,
        al1, ar1, p_el, p_er, N_NODES, 512, 256, 512);
    fused_gat8<true, false, true><<<WB, 256>>>(p_fr, p_el, p_er, p_etatt + 48,
                                               p_a0, p_hBh, p_hBl);

    // ---- layer 2 ----
    gemm_cp<1, 2><<<dim3(1, GY), 512, STG1>>>(
        p_hBh, p_hBl, p_wh + OFF_BCAT, p_wl + OFF_BCAT, p_f2,
        al2, ar2, p_el, p_er, N_NODES, 32, 256, 32);
    fused_gat1<<<WB, 256>>>(p_f2, p_el, p_er, p_etatt + 96, out);
}

// round 16
// speedup vs baseline: 1.0195x; 1.0195x over previous
#include <cuda_runtime.h>
#include <cuda_bf16.h>
#include <math.h>
#include <stdint.h>
#include <string.h>

// ---------------------------------------------------------------------------
// SimpleHGN forward, round 16:
//  - REVERT round-15 gat8 pipelining (register pressure, no latency win:
//    cross-warp scheduling already covers the index chain) -> round-14 gat8
//  - KEEP proj_cp2 (256-thr / 2-CTA-per-SM, round-14-validated pattern)
//  - otherwise identical to the 574.4us round-14 kernel
// ---------------------------------------------------------------------------

#define N_NODES 50000
#define N_EDGES 800000
#define N0 20000
#define N1 17000
#define N2 13000
#define SCAN_B 512
#define SCAN_NB ((N_NODES + SCAN_B - 1) / SCAN_B)

#define OFF_FCW0 0
#define OFF_FCW1 8192
#define OFF_FCW2 24576
#define OFF_W0   28672
#define OFF_W1C  45056
#define OFF_BCAT 176128
#define W_TOTAL  184320

// ------------------------------ side stream (created at library load) ------
struct StreamHolder {
    cudaStream_t s;
    cudaEvent_t a, b;
    StreamHolder() {
        cudaStreamCreateWithFlags(&s, cudaStreamNonBlocking);
        cudaEventCreateWithFlags(&a, cudaEventDisableTiming);
        cudaEventCreateWithFlags(&b, cudaEventDisableTiming);
    }
};
static StreamHolder g_sh;

// ------------------------------ scratch ------------------------------------
__device__ int   g_cnt[N_NODES];
__device__ int   g_rowptr[N_NODES + 1];
__device__ int   g_cursor[N_NODES];
__device__ int   g_bsum[SCAN_NB];
__device__ int   g_boff[SCAN_NB];
__device__ int   g_srcS[N_EDGES];
__device__ int   g_etS[N_EDGES];

__device__ float g_fr[(size_t)N_NODES * 512];
__device__ float g_f2[N_NODES * 32];
__device__ float g_a0[N_EDGES * 8];
__device__ float g_el[N_NODES * 8];
__device__ float g_er[N_NODES * 8];
__device__ float g_etatt[3 * 6 * 8];
__device__ uint16_t g_wh[W_TOTAL];
__device__ uint16_t g_wl[W_TOTAL];

__device__ uint16_t g_x0h[N0 * 128], g_x0l[N0 * 128];
__device__ uint16_t g_x1h[N1 * 256], g_x1l[N1 * 256];
__device__ uint16_t g_x2h[N2 * 64],  g_x2l[N2 * 64];
__device__ uint16_t g_h0h[N_NODES * 64],  g_h0l[N_NODES * 64];
__device__ uint16_t g_hAh[N_NODES * 256], g_hAl[N_NODES * 256];
__device__ uint16_t g_hBh[N_NODES * 256], g_hBl[N_NODES * 256];

// ------------------------------ helpers ------------------------------------
__device__ __forceinline__ uint32_t smem_u32(const void* p) {
    uint32_t a;
    asm("{ .reg .u64 t; cvta.to.shared.u64 t, %1; cvt.u32.u64 %0, t; }"
        : "=r"(a) : "l"(p));
    return a;
}

__device__ __forceinline__ void cp16(uint32_t dst, const void* src, int sz) {
    asm volatile("cp.async.cg.shared.global [%0], [%1], 16, %2;"
                 :: "r"(dst), "l"(src), "r"(sz) : "memory");
}
#define CP_COMMIT() asm volatile("cp.async.commit_group;" ::: "memory")
#define CP_WAIT1()  asm volatile("cp.async.wait_group 1;" ::: "memory")

#define LDSM_X4(r, addr) \
    asm volatile("ldmatrix.sync.aligned.m8n8.x4.shared.b16 {%0,%1,%2,%3}, [%4];" \
                 : "=r"((r)[0]), "=r"((r)[1]), "=r"((r)[2]), "=r"((r)[3]) \
                 : "r"(addr))

__device__ __forceinline__ void mma_bf16(float* c, uint32_t a0, uint32_t a1,
                                         uint32_t a2, uint32_t a3,
                                         uint32_t b0, uint32_t b1) {
    asm volatile(
        "mma.sync.aligned.m16n8k16.row.col.f32.bf16.bf16.f32 "
        "{%0,%1,%2,%3}, {%4,%5,%6,%7}, {%8,%9}, {%0,%1,%2,%3};"
        : "+f"(c[0]), "+f"(c[1]), "+f"(c[2]), "+f"(c[3])
        : "r"(a0), "r"(a1), "r"(a2), "r"(a3), "r"(b0), "r"(b1));
}

__device__ __forceinline__ uint16_t bf_bits(__nv_bfloat16 h) {
    uint16_t b;
    memcpy(&b, &h, 2);
    return b;
}

__device__ __forceinline__ void split_bf16(float v, uint16_t& hb, uint16_t& lb) {
    __nv_bfloat16 h = __float2bfloat16(v);
    float hf = __bfloat162float(h);
    __nv_bfloat16 l = __float2bfloat16(v - hf);
    hb = bf_bits(h);
    lb = bf_bits(l);
}

// ------------------------------ merged convert + weight prep ---------------
__global__ void conv_prep(const float* __restrict__ x0, const float* __restrict__ x1,
                          const float* __restrict__ x2,
                          const float* __restrict__ fcw0, const float* __restrict__ fcw1,
                          const float* __restrict__ fcw2, const float* __restrict__ W0,
                          const float* __restrict__ W1, const float* __restrict__ resW1,
                          const float* __restrict__ W2, const float* __restrict__ resW2) {
    const int S0 = N0 * 128, S1 = N1 * 256, S2 = N2 * 64;
    const int SX = S0 + S1 + S2;
    const int TOT = SX + W_TOTAL;
    for (int i = blockIdx.x * blockDim.x + threadIdx.x; i < TOT;
         i += gridDim.x * blockDim.x) {
        if (i < SX) {
            float v;
            uint16_t *ph, *pl;
            int j;
            if (i < S0)           { j = i;           v = x0[j]; ph = g_x0h; pl = g_x0l; }
            else if (i < S0 + S1) { j = i - S0;      v = x1[j]; ph = g_x1h; pl = g_x1l; }
            else                  { j = i - S0 - S1; v = x2[j]; ph = g_x2h; pl = g_x2l; }
            uint16_t hb, lb;
            split_bf16(v, hb, lb);
            ph[j] = hb;
            pl[j] = lb;
        } else {
            int idx = i - SX;
            int N, base, rel;
            int mode = 0;
            const float* src = nullptr;
            if (idx < 8192)        { src = fcw0; N = 64;  base = OFF_FCW0; rel = idx; }
            else if (idx < 24576)  { src = fcw1; N = 64;  base = OFF_FCW1; rel = idx - 8192; }
            else if (idx < 28672)  { src = fcw2; N = 64;  base = OFF_FCW2; rel = idx - 24576; }
            else if (idx < 45056)  { src = W0;   N = 256; base = OFF_W0;   rel = idx - 28672; }
            else if (idx < 176128) { N = 512; base = OFF_W1C;  rel = idx - 45056; mode = 1; }
            else                   { N = 32;  base = OFF_BCAT; rel = idx - 176128; mode = 2; }
            int k = rel / N, n = rel - k * N;
            float v;
            if (mode == 1)      v = (n < 256) ? W1[k * 256 + n] : resW1[k * 256 + (n - 256)];
            else if (mode == 2) v = (n < 16) ? W2[k * 16 + n] : resW2[k * 16 + (n - 16)];
            else                v = src[rel];
            uint16_t hb, lb;
            split_bf16(v, hb, lb);
            int c = k >> 5, kp = (k & 31) >> 1;
            size_t word = (size_t)c * (N * 16) + (size_t)n * 16 + kp;
            g_wh[base + word * 2 + (k & 1)] = hb;
            g_wl[base + word * 2 + (k & 1)] = lb;
        }
    }
}

// ------------------------------ big GEMM: 256 thr, BN=128, 2 CTA/SM --------
template <bool EL>
__global__ void __launch_bounds__(256, 2) gemm_cp2(
    const uint16_t* __restrict__ AhG, const uint16_t* __restrict__ AlG,
    const uint16_t* __restrict__ BhG, const uint16_t* __restrict__ BlG,
    float* __restrict__ C,
    const float* __restrict__ al, const float* __restrict__ ar,
    float* __restrict__ elp, float* __restrict__ erp,
    int M, int Ntot, int K, int ldc) {
    constexpr int NT = 8;
    constexpr int BN = 128;
    constexpr int PAD = 20;
    constexpr int A_PLANE = 128 * PAD * 4;
    constexpr int B_PLANE = BN * PAD * 4;
    constexpr int OFF_AL2 = A_PLANE;
    constexpr int OFF_BH2 = 2 * A_PLANE;
    constexpr int OFF_BL2 = 2 * A_PLANE + B_PLANE;
    constexpr int STAGE = 2 * A_PLANE + 2 * B_PLANE;
    extern __shared__ char smem[];

    int row0 = blockIdx.y * 128, col0 = blockIdx.x * BN;
    uint32_t sb = smem_u32(smem);
    int tid = threadIdx.x, wid = tid >> 5, lane = tid & 31;
    int g = lane >> 2, tig = lane & 3;
    int warpM = wid & 3, warpN = wid >> 2;

    float acc[2][NT][4];
    #pragma unroll
    for (int mt = 0; mt < 2; mt++)
        #pragma unroll
        for (int nt = 0; nt < NT; nt++)
            #pragma unroll
            for (int j = 0; j < 4; j++) acc[mt][nt][j] = 0.f;

    auto load_stage = [&](int s, int kt) {
        uint32_t base = sb + s * STAGE;
        #pragma unroll
        for (int i = 0; i < 2; i++) {
            int lin = tid + i * 256;
            int r = lin >> 2, c4 = lin & 3;
            int gr = row0 + r;
            int sz = (gr < M) ? 16 : 0;
            size_t boff = ((size_t)gr * K + kt * 32) * 2 + c4 * 16;
            cp16(base + (r * PAD + c4 * 4) * 4, (const char*)AhG + boff, sz);
            cp16(base + OFF_AL2 + (r * PAD + c4 * 4) * 4, (const char*)AlG + boff, sz);
        }
        #pragma unroll
        for (int i = 0; i < 2; i++) {
            int lin = tid + i * 256;
            int n = lin >> 2, c4 = lin & 3;
            size_t boff = ((size_t)kt * Ntot * 16 + (size_t)(col0 + n) * 16) * 4 + c4 * 16;
            cp16(base + OFF_BH2 + (n * PAD + c4 * 4) * 4, (const char*)BhG + boff, 16);
            cp16(base + OFF_BL2 + (n * PAD + c4 * 4) * 4, (const char*)BlG + boff, 16);
        }
    };

    uint32_t a_base = (uint32_t)((warpM * 32 + (lane & 15)) * PAD +
                                 ((lane & 16) ? 4 : 0)) * 4;
    uint32_t b_base = (uint32_t)((warpN * 64 + (lane & 7) +
                                  ((lane & 16) ? 8 : 0)) * PAD +
                                 ((lane & 8) ? 4 : 0)) * 4;

    int nk = K >> 5;
    load_stage(0, 0);
    CP_COMMIT();
    load_stage(1, 1);
    CP_COMMIT();

    for (int kt = 0; kt < nk; kt++) {
        CP_WAIT1();
        __syncthreads();
        int s = kt & 1;
        uint32_t sA  = sb + s * STAGE;
        uint32_t sAl = sA + OFF_AL2;
        uint32_t sBh = sA + OFF_BH2;
        uint32_t sBl = sA + OFF_BL2;

        #pragma unroll
        for (int kh = 0; kh < 2; kh++) {
            uint32_t ko = kh * 32;
            uint32_t aH[2][4], aL[2][4];
            #pragma unroll
            for (int mt = 0; mt < 2; mt++) {
                LDSM_X4(aH[mt], sA + a_base + mt * 16 * PAD * 4 + ko);
                LDSM_X4(aL[mt], sAl + a_base + mt * 16 * PAD * 4 + ko);
            }
            #pragma unroll
            for (int nt2 = 0; nt2 < NT / 2; nt2++) {
                uint32_t bh[4], bl[4];
                LDSM_X4(bh, sBh + b_base + nt2 * 16 * PAD * 4 + ko);
                LDSM_X4(bl, sBl + b_base + nt2 * 16 * PAD * 4 + ko);
                #pragma unroll
                for (int half = 0; half < 2; half++) {
                    int nt = nt2 * 2 + half;
                    uint32_t bh0 = bh[half * 2], bh1 = bh[half * 2 + 1];
                    uint32_t bl0 = bl[half * 2], bl1 = bl[half * 2 + 1];
                    #pragma unroll
                    for (int mt = 0; mt < 2; mt++) {
                        mma_bf16(acc[mt][nt], aH[mt][0], aH[mt][1], aH[mt][2], aH[mt][3], bh0, bh1);
                        mma_bf16(acc[mt][nt], aL[mt][0], aL[mt][1], aL[mt][2], aL[mt][3], bh0, bh1);
                        mma_bf16(acc[mt][nt], aH[mt][0], aH[mt][1], aH[mt][2], aH[mt][3], bl0, bl1);
                    }
                }
            }
        }
        __syncthreads();
        if (kt + 2 < nk) load_stage(s, kt + 2);
        CP_COMMIT();
    }

    #pragma unroll
    for (int mt = 0; mt < 2; mt++) {
        #pragma unroll
        for (int nt = 0; nt < NT; nt++) {
            int r0 = row0 + warpM * 32 + mt * 16 + g;
            int c = col0 + warpN * 64 + nt * 8 + tig * 2;
            #pragma unroll
            for (int half = 0; half < 2; half++) {
                int r = r0 + half * 8;
                if (r >= M) continue;
                *(float2*)&C[(size_t)r * ldc + c] =
                    make_float2(acc[mt][nt][half * 2 + 0], acc[mt][nt][half * 2 + 1]);
            }
        }
    }

    if (EL && col0 < 256) {
        float elacc[2][2][2], eracc[2][2][2];
        #pragma unroll
        for (int mt = 0; mt < 2; mt++)
            #pragma unroll
            for (int half = 0; half < 2; half++)
                #pragma unroll
                for (int hl = 0; hl < 2; hl++) {
                    elacc[mt][half][hl] = 0.f;
                    eracc[mt][half][hl] = 0.f;
                }
        #pragma unroll
        for (int nt = 0; nt < NT; nt++) {
            int hl = nt >> 2;
            int h = (col0 >> 5) + warpN * 2 + hl;
            int o = (nt * 8 + tig * 2) & 31;
            float al0v = al[h * 32 + o], al1v = al[h * 32 + o + 1];
            float ar0v = ar[h * 32 + o], ar1v = ar[h * 32 + o + 1];
            #pragma unroll
            for (int mt = 0; mt < 2; mt++)
                #pragma unroll
                for (int half = 0; half < 2; half++) {
                    float v0 = acc[mt][nt][half * 2 + 0];
                    float v1 = acc[mt][nt][half * 2 + 1];
                    elacc[mt][half][hl] += v0 * al0v + v1 * al1v;
                    eracc[mt][half][hl] += v0 * ar0v + v1 * ar1v;
                }
        }
        #pragma unroll
        for (int mt = 0; mt < 2; mt++)
            #pragma unroll
            for (int half = 0; half < 2; half++)
                #pragma unroll
                for (int hl = 0; hl < 2; hl++) {
                    float ev = elacc[mt][half][hl];
                    float rv = eracc[mt][half][hl];
                    ev += __shfl_xor_sync(0xffffffffu, ev, 1);
                    ev += __shfl_xor_sync(0xffffffffu, ev, 2);
                    rv += __shfl_xor_sync(0xffffffffu, rv, 1);
                    rv += __shfl_xor_sync(0xffffffffu, rv, 2);
                    if (tig == 0) {
                        int r = row0 + warpM * 32 + mt * 16 + g + half * 8;
                        int h2 = (col0 >> 5) + warpN * 2 + hl;
                        if (r < M) {
                            elp[r * 8 + h2] = ev;
                            erp[r * 8 + h2] = rv;
                        }
                    }
                }
    }
}

// ------------------------------ proj GEMM: 256 thr, BN=64, 2 CTA/SM --------
__device__ __forceinline__ void proj_body2(
    const uint16_t* __restrict__ AhG, const uint16_t* __restrict__ AlG,
    const uint16_t* __restrict__ BhG, const uint16_t* __restrict__ BlG,
    const float* __restrict__ bias, uint16_t* __restrict__ Ch,
    uint16_t* __restrict__ Cl, int M, int K, int row0, char* smem) {
    constexpr int NT = 4;
    constexpr int BN = 64;
    constexpr int PAD = 20;
    constexpr int A_PLANE = 128 * PAD * 4;
    constexpr int B_PLANE = BN * PAD * 4;
    constexpr int OFF_AL2 = A_PLANE;
    constexpr int OFF_BH2 = 2 * A_PLANE;
    constexpr int OFF_BL2 = 2 * A_PLANE + B_PLANE;
    constexpr int STAGE = 2 * A_PLANE + 2 * B_PLANE;

    uint32_t sb = smem_u32(smem);
    int tid = threadIdx.x, wid = tid >> 5, lane = tid & 31;
    int g = lane >> 2, tig = lane & 3;
    int warpM = wid & 3, warpN = wid >> 2;

    float acc[2][NT][4];
    #pragma unroll
    for (int mt = 0; mt < 2; mt++)
        #pragma unroll
        for (int nt = 0; nt < NT; nt++)
            #pragma unroll
            for (int j = 0; j < 4; j++) acc[mt][nt][j] = 0.f;

    auto load_stage = [&](int s, int kt) {
        uint32_t base = sb + s * STAGE;
        #pragma unroll
        for (int i = 0; i < 2; i++) {
            int lin = tid + i * 256;
            int r = lin >> 2, c4 = lin & 3;
            int gr = row0 + r;
            int sz = (gr < M) ? 16 : 0;
            size_t boff = ((size_t)gr * K + kt * 32) * 2 + c4 * 16;
            cp16(base + (r * PAD + c4 * 4) * 4, (const char*)AhG + boff, sz);
            cp16(base + OFF_AL2 + (r * PAD + c4 * 4) * 4, (const char*)AlG + boff, sz);
        }
        if (tid < BN * 4) {
            int n = tid >> 2, c4 = tid & 3;
            size_t boff = ((size_t)kt * 64 * 16 + (size_t)n * 16) * 4 + c4 * 16;
            cp16(base + OFF_BH2 + (n * PAD + c4 * 4) * 4, (const char*)BhG + boff, 16);
            cp16(base + OFF_BL2 + (n * PAD + c4 * 4) * 4, (const char*)BlG + boff, 16);
        }
    };

    uint32_t a_base = (uint32_t)((warpM * 32 + (lane & 15)) * PAD +
                                 ((lane & 16) ? 4 : 0)) * 4;
    uint32_t b_base = (uint32_t)((warpN * 32 + (lane & 7) +
                                  ((lane & 16) ? 8 : 0)) * PAD +
                                 ((lane & 8) ? 4 : 0)) * 4;

    int nk = K >> 5;
    load_stage(0, 0);
    CP_COMMIT();
    load_stage(1, 1 < nk ? 1 : 0);
    CP_COMMIT();

    for (int kt = 0; kt < nk; kt++) {
        CP_WAIT1();
        __syncthreads();
        int s = kt & 1;
        uint32_t sA  = sb + s * STAGE;
        uint32_t sAl = sA + OFF_AL2;
        uint32_t sBh = sA + OFF_BH2;
        uint32_t sBl = sA + OFF_BL2;

        #pragma unroll
        for (int kh = 0; kh < 2; kh++) {
            uint32_t ko = kh * 32;
            uint32_t aH[2][4], aL[2][4];
            #pragma unroll
            for (int mt = 0; mt < 2; mt++) {
                LDSM_X4(aH[mt], sA + a_base + mt * 16 * PAD * 4 + ko);
                LDSM_X4(aL[mt], sAl + a_base + mt * 16 * PAD * 4 + ko);
            }
            #pragma unroll
            for (int nt2 = 0; nt2 < NT / 2; nt2++) {
                uint32_t bh[4], bl[4];
                LDSM_X4(bh, sBh + b_base + nt2 * 16 * PAD * 4 + ko);
                LDSM_X4(bl, sBl + b_base + nt2 * 16 * PAD * 4 + ko);
                #pragma unroll
                for (int half = 0; half < 2; half++) {
                    int nt = nt2 * 2 + half;
                    uint32_t bh0 = bh[half * 2], bh1 = bh[half * 2 + 1];
                    uint32_t bl0 = bl[half * 2], bl1 = bl[half * 2 + 1];
                    #pragma unroll
                    for (int mt = 0; mt < 2; mt++) {
                        mma_bf16(acc[mt][nt], aH[mt][0], aH[mt][1], aH[mt][2], aH[mt][3], bh0, bh1);
                        mma_bf16(acc[mt][nt], aL[mt][0], aL[mt][1], aL[mt][2], aL[mt][3], bh0, bh1);
                        mma_bf16(acc[mt][nt], aH[mt][0], aH[mt][1], aH[mt][2], aH[mt][3], bl0, bl1);
                    }
                }
            }
        }
        __syncthreads();
        if (kt + 2 < nk) load_stage(s, kt + 2);
        CP_COMMIT();
    }

    #pragma unroll
    for (int mt = 0; mt < 2; mt++) {
        #pragma unroll
        for (int nt = 0; nt < NT; nt++) {
            int r0 = row0 + warpM * 32 + mt * 16 + g;
            int c = warpN * 32 + nt * 8 + tig * 2;
            float b0a = bias[c], b1a = bias[c + 1];
            #pragma unroll
            for (int half = 0; half < 2; half++) {
                int r = r0 + half * 8;
                if (r >= M) continue;
                float v0 = acc[mt][nt][half * 2 + 0] + b0a;
                float v1 = acc[mt][nt][half * 2 + 1] + b1a;
                uint16_t h0b, l0b, h1b, l1b;
                split_bf16(v0, h0b, l0b);
                split_bf16(v1, h1b, l1b);
                *(uint32_t*)&Ch[(size_t)r * 64 + c] = (uint32_t)h0b | ((uint32_t)h1b << 16);
                *(uint32_t*)&Cl[(size_t)r * 64 + c] = (uint32_t)l0b | ((uint32_t)l1b << 16);
            }
        }
    }
}

__global__ void __launch_bounds__(256, 2) proj_cp2(const float* __restrict__ fcb0,
                                                   const float* __restrict__ fcb1,
                                                   const float* __restrict__ fcb2) {
    extern __shared__ char smem[];
    const int NB0 = (N0 + 127) / 128;
    const int NB01 = NB0 + (N1 + 127) / 128;
    int by = blockIdx.y;
    if (by < NB0) {
        proj_body2(g_x0h, g_x0l, g_wh + OFF_FCW0, g_wl + OFF_FCW0, fcb0,
                   g_h0h, g_h0l, N0, 128, by * 128, smem);
    } else if (by < NB01) {
        proj_body2(g_x1h, g_x1l, g_wh + OFF_FCW1, g_wl + OFF_FCW1, fcb1,
                   g_h0h + (size_t)N0 * 64, g_h0l + (size_t)N0 * 64,
                   N1, 256, (by - NB0) * 128, smem);
    } else {
        proj_body2(g_x2h, g_x2l, g_wh + OFF_FCW2, g_wl + OFF_FCW2, fcb2,
                   g_h0h + (size_t)(N0 + N1) * 64, g_h0l + (size_t)(N0 + N1) * 64,
                   N2, 64, (by - NB01) * 128, smem);
    }
}

// ------------------------------ small GEMM (512 thr, layer 2) --------------
template <int NT, int ELMODE>
__global__ void __launch_bounds__(512) gemm_cp(
    const uint16_t* __restrict__ AhG, const uint16_t* __restrict__ AlG,
    const uint16_t* __restrict__ BhG, const uint16_t* __restrict__ BlG,
    float* __restrict__ C,
    const float* __restrict__ al, const float* __restrict__ ar,
    float* __restrict__ elp, float* __restrict__ erp,
    int M, int Ntot, int K, int ldc) {
    constexpr int BN = NT * 32;
    constexpr int PAD = 20;
    constexpr int A_PLANE = 128 * PAD * 4;
    constexpr int B_PLANE = BN * PAD * 4;
    constexpr int OFF_AL2 = A_PLANE;
    constexpr int OFF_BH2 = 2 * A_PLANE;
    constexpr int OFF_BL2 = 2 * A_PLANE + B_PLANE;
    constexpr int STAGE = 2 * A_PLANE + 2 * B_PLANE;
    extern __shared__ char smem[];

    int row0 = blockIdx.y * 128, col0 = blockIdx.x * BN;
    uint32_t sb = smem_u32(smem);
    int tid = threadIdx.x, wid = tid >> 5, lane = tid & 31;
    int g = lane >> 2, tig = lane & 3;
    int warpM = wid & 3, warpN = wid >> 2;

    float acc[2][NT][4];
    #pragma unroll
    for (int mt = 0; mt < 2; mt++)
        #pragma unroll
        for (int nt = 0; nt < NT; nt++)
            #pragma unroll
            for (int j = 0; j < 4; j++) acc[mt][nt][j] = 0.f;

    auto load_stage = [&](int s, int kt) {
        uint32_t base = sb + s * STAGE;
        {
            int r = tid >> 2, c4 = tid & 3;
            int gr = row0 + r;
            int sz = (gr < M) ? 16 : 0;
            size_t boff = ((size_t)gr * K + kt * 32) * 2 + c4 * 16;
            cp16(base + (r * PAD + c4 * 4) * 4, (const char*)AhG + boff, sz);
            cp16(base + OFF_AL2 + (r * PAD + c4 * 4) * 4, (const char*)AlG + boff, sz);
        }
        #pragma unroll
        for (int lin = tid; lin < BN * 4; lin += 512) {
            int n = lin >> 2, c4 = lin & 3;
            size_t boff = ((size_t)kt * Ntot * 16 + (size_t)(col0 + n) * 16) * 4 + c4 * 16;
            cp16(base + OFF_BH2 + (n * PAD + c4 * 4) * 4, (const char*)BhG + boff, 16);
            cp16(base + OFF_BL2 + (n * PAD + c4 * 4) * 4, (const char*)BlG + boff, 16);
        }
    };

    uint32_t a_base = (uint32_t)((warpM * 32 + (lane & 15)) * PAD +
                                 ((lane & 16) ? 4 : 0)) * 4;

    int nk = K >> 5;
    load_stage(0, 0);
    CP_COMMIT();
    load_stage(1, 1);
    CP_COMMIT();

    for (int kt = 0; kt < nk; kt++) {
        CP_WAIT1();
        __syncthreads();
        if (kt + 2 < nk) load_stage((kt + 2) % 3, kt + 2);
        CP_COMMIT();
        int s = kt % 3;
        uint32_t sA  = sb + s * STAGE;
        uint32_t sAl = sA + OFF_AL2;

        #pragma unroll
        for (int kh = 0; kh < 2; kh++) {
            uint32_t ko = kh * 32;
            uint32_t aH[2][4], aL[2][4];
            #pragma unroll
            for (int mt = 0; mt < 2; mt++) {
                LDSM_X4(aH[mt], sA + a_base + mt * 16 * PAD * 4 + ko);
                LDSM_X4(aL[mt], sAl + a_base + mt * 16 * PAD * 4 + ko);
            }
            const uint32_t* BsH = (const uint32_t*)(smem + s * STAGE + OFF_BH2);
            const uint32_t* BsL = (const uint32_t*)(smem + s * STAGE + OFF_BL2);
            int kp0 = kh * 8;
            int n0 = warpN * 8;
            int bbase = (n0 + g) * PAD + kp0 + tig;
            uint32_t bh0 = BsH[bbase], bh1 = BsH[bbase + 4];
            uint32_t bl0 = BsL[bbase], bl1 = BsL[bbase + 4];
            #pragma unroll
            for (int mt = 0; mt < 2; mt++) {
                mma_bf16(acc[mt][0], aH[mt][0], aH[mt][1], aH[mt][2], aH[mt][3], bh0, bh1);
                mma_bf16(acc[mt][0], aL[mt][0], aL[mt][1], aL[mt][2], aL[mt][3], bh0, bh1);
                mma_bf16(acc[mt][0], aH[mt][0], aH[mt][1], aH[mt][2], aH[mt][3], bl0, bl1);
            }
        }
        __syncthreads();
    }

    #pragma unroll
    for (int mt = 0; mt < 2; mt++) {
        int r0 = row0 + warpM * 32 + mt * 16 + g;
        int c = col0 + warpN * 8 + tig * 2;
        #pragma unroll
        for (int half = 0; half < 2; half++) {
            int r = r0 + half * 8;
            if (r >= M) continue;
            *(float2*)&C[(size_t)r * ldc + c] =
                make_float2(acc[mt][0][half * 2 + 0], acc[mt][0][half * 2 + 1]);
        }
    }

    if (ELMODE == 2) {
        float evp[2][2], rvp[2][2];
        #pragma unroll
        for (int mt = 0; mt < 2; mt++)
            #pragma unroll
            for (int half = 0; half < 2; half++) {
                evp[mt][half] = 0.f;
                rvp[mt][half] = 0.f;
            }
        if (warpN < 2) {
            #pragma unroll
            for (int mt = 0; mt < 2; mt++)
                #pragma unroll
                for (int half = 0; half < 2; half++) {
                    int c = warpN * 8 + tig * 2;
                    float v0 = acc[mt][0][half * 2 + 0];
                    float v1 = acc[mt][0][half * 2 + 1];
                    float ev = v0 * al[c] + v1 * al[c + 1];
                    float rv = v0 * ar[c] + v1 * ar[c + 1];
                    ev += __shfl_xor_sync(0xffffffffu, ev, 1);
                    ev += __shfl_xor_sync(0xffffffffu, ev, 2);
                    rv += __shfl_xor_sync(0xffffffffu, rv, 1);
                    rv += __shfl_xor_sync(0xffffffffu, rv, 2);
                    evp[mt][half] = ev;
                    rvp[mt][half] = rv;
                }
        }
        float* buf = (float*)smem;
        __syncthreads();
        if (warpN == 1 && tig == 0) {
            #pragma unroll
            for (int mt = 0; mt < 2; mt++)
                #pragma unroll
                for (int half = 0; half < 2; half++) {
                    int rr = warpM * 32 + mt * 16 + g + half * 8;
                    buf[rr * 2 + 0] = evp[mt][half];
                    buf[rr * 2 + 1] = rvp[mt][half];
                }
        }
        __syncthreads();
        if (warpN == 0 && tig == 0) {
            #pragma unroll
            for (int mt = 0; mt < 2; mt++)
                #pragma unroll
                for (int half = 0; half < 2; half++) {
                    int rr = warpM * 32 + mt * 16 + g + half * 8;
                    int r = row0 + rr;
                    if (r < M) {
                        elp[r] = evp[mt][half] + buf[rr * 2 + 0];
                        erp[r] = rvp[mt][half] + buf[rr * 2 + 1];
                    }
                }
        }
    }
}

// ------------------------------ CSR build ----------------------------------
__global__ void hist_kernel(const int* __restrict__ dst) {
    int e = blockIdx.x * blockDim.x + threadIdx.x;
    if (e < N_EDGES) atomicAdd(&g_cnt[dst[e]], 1);
}

__global__ void scan_block_kernel() {
    __shared__ int sh[SCAN_B];
    int t = threadIdx.x;
    int i = blockIdx.x * SCAN_B + t;
    int v = (i < N_NODES) ? g_cnt[i] : 0;
    sh[t] = v;
    __syncthreads();
    #pragma unroll
    for (int off = 1; off < SCAN_B; off <<= 1) {
        int tmp = (t >= off) ? sh[t - off] : 0;
        __syncthreads();
        sh[t] += tmp;
        __syncthreads();
    }
    if (i < N_NODES) g_rowptr[i + 1] = sh[t];
    if (t == SCAN_B - 1) g_bsum[blockIdx.x] = sh[t];
}

__global__ void scan_top_kernel() {
    __shared__ int sh[128];
    int t = threadIdx.x;
    int v = (t < SCAN_NB) ? g_bsum[t] : 0;
    sh[t] = v;
    __syncthreads();
    #pragma unroll
    for (int off = 1; off < 128; off <<= 1) {
        int tmp = (t >= off) ? sh[t - off] : 0;
        __syncthreads();
        sh[t] += tmp;
        __syncthreads();
    }
    if (t < SCAN_NB) g_boff[t] = sh[t] - v;
}

__global__ void scan_add_kernel() {
    int t = threadIdx.x;
    int i = blockIdx.x * SCAN_B + t;
    if (i < N_NODES) {
        int v = g_rowptr[i + 1] + g_boff[blockIdx.x];
        g_rowptr[i + 1] = v;
        g_cursor[i] = v - g_cnt[i];
    }
    if (i == 0) g_rowptr[0] = 0;
}

__global__ void scatter_kernel(const int* __restrict__ src, const int* __restrict__ dst,
                               const int* __restrict__ et) {
    int e = blockIdx.x * blockDim.x + threadIdx.x;
    if (e >= N_EDGES) return;
    int d = dst[e];
    int pos = atomicAdd(&g_cursor[d], 1);
    g_srcS[pos] = src[e];
    g_etS[pos]  = et[e];
}

// ------------------------------ edge-type attention ------------------------
__global__ void etype_att_kernel(const float* __restrict__ eemb, const float* __restrict__ We,
                                 const float* __restrict__ ae, float* __restrict__ out, int H) {
    int t = blockIdx.x / H;
    int h = blockIdx.x % H;
    int d = threadIdx.x;
    int Wcols = H * 64;
    float v = 0.f;
    #pragma unroll 4
    for (int k = 0; k < 64; k++)
        v += eemb[t * 64 + k] * We[k * Wcols + h * 64 + d];
    v *= ae[h * 64 + d];
    __shared__ float sh[64];
    sh[d] = v;
    __syncthreads();
    #pragma unroll
    for (int o = 32; o > 0; o >>= 1) {
        if (d < o) sh[d] += sh[d + o];
        __syncthreads();
    }
    if (d == 0) out[t * H + h] = sh[0];
}

// ------------------------------ fused GAT edge kernel (H=8, round-14) ------
template <bool BLEND, bool SAVE_A, bool RES>
__global__ void fused_gat8(const float* __restrict__ feat, const float* __restrict__ el,
                           const float* __restrict__ er, const float* __restrict__ etatt,
                           float* __restrict__ a0,
                           uint16_t* __restrict__ outh, uint16_t* __restrict__ outl) {
    int warp = (blockIdx.x * blockDim.x + threadIdx.x) >> 5;
    int lane = threadIdx.x & 31;
    if (warp >= N_NODES) return;
    int n = warp;
    int h = lane & 7, eslot = lane >> 3;
    float er_n = er[n * 8 + h];
    float eat[6];
    #pragma unroll
    for (int t = 0; t < 6; t++) eat[t] = etatt[t * 8 + h];
    int b = g_rowptr[n], e = g_rowptr[n + 1];

    float m = -1e30f, s = 0.f;
    for (int i0 = b; i0 < e; i0 += 4) {
        int i = i0 + eslot;
        if (i < e) {
            float ev = el[g_srcS[i] * 8 + h] + er_n + eat[g_etS[i]];
            ev = (ev > 0.f) ? ev : 0.2f * ev;
            float nm = fmaxf(m, ev);
            s = s * __expf(m - nm) + __expf(ev - nm);
            m = nm;
        }
    }
    #pragma unroll
    for (int off = 8; off <= 16; off <<= 1) {
        float om = __shfl_xor_sync(0xffffffffu, m, off);
        float os = __shfl_xor_sync(0xffffffffu, s, off);
        float nm = fmaxf(m, om);
        s = s * __expf(m - nm) + os * __expf(om - nm);
        m = nm;
    }

    float acc[8];
    #pragma unroll
    for (int h2 = 0; h2 < 8; h2++)
        acc[h2] = RES ? feat[(size_t)n * 512 + 256 + h2 * 32 + lane] : 0.f;

    int i0 = b;
    for (; i0 + 4 <= e; i0 += 4) {
        int i = i0 + eslot;
        int sidx = g_srcS[i];
        float ev = el[sidx * 8 + h] + er_n + eat[g_etS[i]];
        ev = (ev > 0.f) ? ev : 0.2f * ev;
        float a = __expf(ev - m) / s;
        if (BLEND) a = a * 0.95f + 0.05f * a0[(size_t)i * 8 + h];
        if (SAVE_A) a0[(size_t)i * 8 + h] = a;

        int s2[4];
        #pragma unroll
        for (int e2 = 0; e2 < 4; e2++)
            s2[e2] = __shfl_sync(0xffffffffu, sidx, e2 * 8);
        float tmp[4][8];
        #pragma unroll
        for (int e2 = 0; e2 < 4; e2++) {
            const float* f = feat + (size_t)s2[e2] * 512;
            #pragma unroll
            for (int h2 = 0; h2 < 8; h2++)
                tmp[e2][h2] = f[h2 * 32 + lane];
        }
        #pragma unroll
        for (int e2 = 0; e2 < 4; e2++)
            #pragma unroll
            for (int h2 = 0; h2 < 8; h2++) {
                float ah = __shfl_sync(0xffffffffu, a, e2 * 8 + h2);
                acc[h2] += ah * tmp[e2][h2];
            }
    }
    if (i0 < e) {
        int i = i0 + eslot;
        float a = 0.f;
        int sidx = 0;
        if (i < e) {
            sidx = g_srcS[i];
            float ev = el[sidx * 8 + h] + er_n + eat[g_etS[i]];
            ev = (ev > 0.f) ? ev : 0.2f * ev;
            a = __expf(ev - m) / s;
            if (BLEND) a = a * 0.95f + 0.05f * a0[(size_t)i * 8 + h];
            if (SAVE_A) a0[(size_t)i * 8 + h] = a;
        }
        #pragma unroll
        for (int e2 = 0; e2 < 4; e2++) {
            if (i0 + e2 < e) {
                int s2 = __shfl_sync(0xffffffffu, sidx, e2 * 8);
                const float* f = feat + (size_t)s2 * 512;
                #pragma unroll
                for (int h2 = 0; h2 < 8; h2++) {
                    float ah = __shfl_sync(0xffffffffu, a, e2 * 8 + h2);
                    acc[h2] += ah * f[h2 * 32 + lane];
                }
            }
        }
    }

    #pragma unroll
    for (int h2 = 0; h2 < 8; h2++) {
        float v = acc[h2];
        v = (v > 0.f) ? v : expm1f(v);
        uint16_t hb, lb;
        split_bf16(v, hb, lb);
        outh[(size_t)n * 256 + h2 * 32 + lane] = hb;
        outl[(size_t)n * 256 + h2 * 32 + lane] = lb;
    }
}

// ------------------------------ fused GAT edge kernel (H=1, out 16) --------
__global__ void fused_gat1(const float* __restrict__ f2, const float* __restrict__ el,
                           const float* __restrict__ er, const float* __restrict__ etatt,
                           float* __restrict__ out) {
    int warp = (blockIdx.x * blockDim.x + threadIdx.x) >> 5;
    int lane = threadIdx.x & 31;
    if (warp >= N_NODES) return;
    int n = warp;
    int eslot = lane >> 4;
    int sub = lane & 15;
    float er_n = er[n];
    float eat[6];
    #pragma unroll
    for (int t = 0; t < 6; t++) eat[t] = etatt[t];
    int b = g_rowptr[n], e = g_rowptr[n + 1];

    float m = -1e30f, s = 0.f;
    for (int i0 = b; i0 < e; i0 += 32) {
        int i = i0 + lane;
        if (i < e) {
            float ev = el[g_srcS[i]] + er_n + eat[g_etS[i]];
            ev = (ev > 0.f) ? ev : 0.2f * ev;
            float nm = fmaxf(m, ev);
            s = s * __expf(m - nm) + __expf(ev - nm);
            m = nm;
        }
    }
    #pragma unroll
    for (int off = 16; off > 0; off >>= 1) {
        float om = __shfl_xor_sync(0xffffffffu, m, off);
        float os = __shfl_xor_sync(0xffffffffu, s, off);
        float nm = fmaxf(m, om);
        s = s * __expf(m - nm) + os * __expf(om - nm);
        m = nm;
    }

    float acc = (eslot == 0) ? f2[(size_t)n * 32 + 16 + sub] : 0.f;
    int i0 = b;
    for (; i0 + 2 <= e; i0 += 2) {
        int i = i0 + eslot;
        int sidx = g_srcS[i];
        float ev = el[sidx] + er_n + eat[g_etS[i]];
        ev = (ev > 0.f) ? ev : 0.2f * ev;
        float a = __expf(ev - m) / s;
        acc += a * f2[(size_t)sidx * 32 + sub];
    }
    if (i0 < e) {
        if (eslot == 0) {
            int sidx = g_srcS[i0];
            float ev = el[sidx] + er_n + eat[g_etS[i0]];
            ev = (ev > 0.f) ? ev : 0.2f * ev;
            float a = __expf(ev - m) / s;
            acc += a * f2[(size_t)sidx * 32 + sub];
        }
    }
    acc += __shfl_down_sync(0xffffffffu, acc, 16);
    if (lane < 16) out[(size_t)n * 16 + lane] = acc;
}

// ---------------------------------------------------------------------------
static inline int cdiv(int a, int b) { return (a + b - 1) / b; }

extern "C" void kernel_launch(void* const* d_in, const int* in_sizes, int n_in,
                              void* d_out, int out_size) {
    const float* x0    = (const float*)d_in[0];
    const float* x1    = (const float*)d_in[1];
    const float* x2    = (const float*)d_in[2];
    const float* fcw0  = (const float*)d_in[3];
    const float* fcb0  = (const float*)d_in[4];
    const float* fcw1  = (const float*)d_in[5];
    const float* fcb1  = (const float*)d_in[6];
    const float* fcw2  = (const float*)d_in[7];
    const float* fcb2  = (const float*)d_in[8];
    const float* W0    = (const float*)d_in[9];
    const float* We0   = (const float*)d_in[10];
    const float* eemb0 = (const float*)d_in[11];
    const float* al0   = (const float*)d_in[12];
    const float* ar0   = (const float*)d_in[13];
    const float* ae0   = (const float*)d_in[14];
    const float* W1    = (const float*)d_in[15];
    const float* We1   = (const float*)d_in[16];
    const float* eemb1 = (const float*)d_in[17];
    const float* al1   = (const float*)d_in[18];
    const float* ar1   = (const float*)d_in[19];
    const float* ae1   = (const float*)d_in[20];
    const float* resW1 = (const float*)d_in[21];
    const float* W2    = (const float*)d_in[22];
    const float* We2   = (const float*)d_in[23];
    const float* eemb2 = (const float*)d_in[24];
    const float* al2   = (const float*)d_in[25];
    const float* ar2   = (const float*)d_in[26];
    const float* ae2   = (const float*)d_in[27];
    const float* resW2 = (const float*)d_in[28];
    const int*   src   = (const int*)d_in[29];
    const int*   dst   = (const int*)d_in[30];
    const int*   etype = (const int*)d_in[31];
    float* out = (float*)d_out;

    float *p_fr, *p_f2, *p_a0, *p_el, *p_er, *p_etatt;
    uint16_t *p_wh, *p_wl, *p_h0h, *p_h0l, *p_hAh, *p_hAl, *p_hBh, *p_hBl;
    int* p_cnt;
    cudaGetSymbolAddress((void**)&p_cnt, g_cnt);
    cudaGetSymbolAddress((void**)&p_fr, g_fr);
    cudaGetSymbolAddress((void**)&p_f2, g_f2);
    cudaGetSymbolAddress((void**)&p_a0, g_a0);
    cudaGetSymbolAddress((void**)&p_el, g_el);
    cudaGetSymbolAddress((void**)&p_er, g_er);
    cudaGetSymbolAddress((void**)&p_etatt, g_etatt);
    cudaGetSymbolAddress((void**)&p_wh, g_wh);
    cudaGetSymbolAddress((void**)&p_wl, g_wl);
    cudaGetSymbolAddress((void**)&p_h0h, g_h0h);
    cudaGetSymbolAddress((void**)&p_h0l, g_h0l);
    cudaGetSymbolAddress((void**)&p_hAh, g_hAh);
    cudaGetSymbolAddress((void**)&p_hAl, g_hAl);
    cudaGetSymbolAddress((void**)&p_hBh, g_hBh);
    cudaGetSymbolAddress((void**)&p_hBl, g_hBl);

    const int STG2 = 2 * (2 * (128 * 20 * 4) + 2 * (128 * 20 * 4));     // 81920
    const int STGP = 2 * (2 * (128 * 20 * 4) + 2 * (64 * 20 * 4));      // 61440
    const int STG1 = 3 * (2 * (128 * 20 * 4) + 2 * (32 * 20 * 4));      // 76800
    cudaFuncSetAttribute(gemm_cp2<true>, cudaFuncAttributeMaxDynamicSharedMemorySize, STG2);
    cudaFuncSetAttribute(proj_cp2, cudaFuncAttributeMaxDynamicSharedMemorySize, STGP);
    cudaFuncSetAttribute(gemm_cp<1, 2>, cudaFuncAttributeMaxDynamicSharedMemorySize, STG1);

    const int WB = cdiv(N_NODES * 32, 256);
    const int GY = cdiv(N_NODES, 128);
    const int PROJ_BLKS = cdiv(N0, 128) + cdiv(N1, 128) + cdiv(N2, 128);
    cudaStream_t s2 = g_sh.s;

    // ---- fork: CSR build + etype_att on side stream ----
    cudaEventRecord(g_sh.a, 0);
    cudaStreamWaitEvent(s2, g_sh.a, 0);
    cudaMemsetAsync(p_cnt, 0, N_NODES * sizeof(int), s2);

    // ---- main chain ----
    conv_prep<<<2048, 256>>>(x0, x1, x2, fcw0, fcw1, fcw2, W0, W1, resW1, W2, resW2);
    proj_cp2<<<dim3(1, PROJ_BLKS), 256, STGP>>>(fcb0, fcb1, fcb2);
    gemm_cp2<true><<<dim3(2, GY), 256, STG2>>>(
        p_h0h, p_h0l, p_wh + OFF_W0, p_wl + OFF_W0, p_fr,
        al0, ar0, p_el, p_er, N_NODES, 256, 64, 512);

    // ---- side stream: CSR build + edge-type attention ----
    hist_kernel<<<cdiv(N_EDGES, 256), 256, 0, s2>>>(dst);
    scan_block_kernel<<<SCAN_NB, SCAN_B, 0, s2>>>();
    scan_top_kernel<<<1, 128, 0, s2>>>();
    scan_add_kernel<<<SCAN_NB, SCAN_B, 0, s2>>>();
    scatter_kernel<<<cdiv(N_EDGES, 256), 256, 0, s2>>>(src, dst, etype);
    etype_att_kernel<<<6 * 8, 64, 0, s2>>>(eemb0, We0, ae0, p_etatt + 0, 8);
    etype_att_kernel<<<6 * 8, 64, 0, s2>>>(eemb1, We1, ae1, p_etatt + 48, 8);
    etype_att_kernel<<<6 * 1, 64, 0, s2>>>(eemb2, We2, ae2, p_etatt + 96, 1);
    cudaEventRecord(g_sh.b, s2);
    cudaStreamWaitEvent(0, g_sh.b, 0);

    // ---- layer 0 ----
    fused_gat8<false, true, false><<<WB, 256>>>(p_fr, p_el, p_er, p_etatt + 0,
                                                p_a0, p_hAh, p_hAl);

    // ---- layer 1 ----
    gemm_cp2<true><<<dim3(4, GY), 256, STG2>>>(
        p_hAh, p_hAl, p_wh + OFF_W1C, p_wl + OFF_W1C, p_fr,
        al1, ar1, p_el, p_er, N_NODES, 512, 256, 512);
    fused_gat8<true, false, true><<<WB, 256>>>(p_fr, p_el, p_er, p_etatt + 48,
                                               p_a0, p_hBh, p_hBl);

    // ---- layer 2 ----
    gemm_cp<1, 2><<<dim3(1, GY), 512, STG1>>>(
        p_hBh, p_hBl, p_wh + OFF_BCAT, p_wl + OFF_BCAT, p_f2,
        al2, ar2, p_el, p_er, N_NODES, 32, 256, 32);
    fused_gat1<<<WB, 256>>>(p_f2, p_el, p_er, p_etatt + 96, out);
}